// round 14
// baseline (speedup 1.0000x reference)
#include <cuda_runtime.h>
#include <cuda_bf16.h>

#define T_SEQ 34
#define NTOK  14
#define NE    476   // 34*14 distinct (position, token) variants

typedef unsigned long long u64;
typedef unsigned int       u32;

// LUTs built by prologue kernel (device globals: no allocation allowed)
__device__ float2 g_q[NE * 3];   // prescaled q, packed (head0, head1) per dim
__device__ u64    g_kv[NE * 5];  // bf16x4 per u64; 40B stride => conflict-free banks
__device__ float2 g_x[NE * 3];   // raw embedded x (pre-LN), for residual
__device__ float  g_sw[288];     // staged epilogue weights (padded layout)

// epilogue weights in constant memory: uniform loads via const port
__constant__ __align__(16) float c_sw[288];

// ---------- packed f32x2 helpers (sm_103a) ----------
__device__ __forceinline__ u64 pk2(float a, float b) {
    u64 r; asm("mov.b64 %0,{%1,%2};" : "=l"(r) : "f"(a), "f"(b)); return r;
}
__device__ __forceinline__ u64 pk2f(float2 f) { return pk2(f.x, f.y); }
__device__ __forceinline__ float2 upk2(u64 v) {
    float2 f; asm("mov.b64 {%0,%1},%2;" : "=f"(f.x), "=f"(f.y) : "l"(v)); return f;
}
__device__ __forceinline__ u64 rep2(float a) {
    u64 r; asm("mov.b64 %0,{%1,%1};" : "=l"(r) : "f"(a)); return r;
}
__device__ __forceinline__ u64 fma2(u64 a, u64 b, u64 c) {
    u64 d; asm("fma.rn.f32x2 %0,%1,%2,%3;" : "=l"(d) : "l"(a), "l"(b), "l"(c)); return d;
}
__device__ __forceinline__ u64 add2(u64 a, u64 b) {
    u64 d; asm("add.rn.f32x2 %0,%1,%2;" : "=l"(d) : "l"(a), "l"(b)); return d;
}
__device__ __forceinline__ u64 mul2(u64 a, u64 b) {
    u64 d; asm("mul.rn.f32x2 %0,%1,%2;" : "=l"(d) : "l"(a), "l"(b)); return d;
}
// bf16x2 (lo=head0, hi=head1) -> f32x2
__device__ __forceinline__ u64 bfpair(u32 u) {
    u32 lo = u << 16, hi = u & 0xffff0000u;
    u64 r; asm("mov.b64 %0,{%1,%2};" : "=l"(r) : "r"(lo), "r"(hi)); return r;
}
__device__ __forceinline__ float fex2(float x) { float r; asm("ex2.approx.f32 %0,%1;" : "=f"(r) : "f"(x)); return r; }
__device__ __forceinline__ float frcp(float x) { float r; asm("rcp.approx.f32 %0,%1;" : "=f"(r) : "f"(x)); return r; }
__device__ __forceinline__ float frsq(float x) { float r; asm("rsqrt.approx.f32 %0,%1;" : "=f"(r) : "f"(x)); return r; }

__device__ __forceinline__ unsigned short bfb(float f) {
    return __bfloat16_as_ushort(__float2bfloat16_rn(f));
}

// const-space u64 fetch (off = float index, must be even)
__device__ __forceinline__ u64 cld(int off) {
    return *reinterpret_cast<const u64*>(c_sw + off);
}

// ---------- prologue: build 476-entry LUTs + stage epilogue weight block ----------
__global__ void build_luts(const float* __restrict__ tok_emb, const float* __restrict__ pos_enc,
                           const float* __restrict__ wq, const float* __restrict__ wk,
                           const float* __restrict__ wv,
                           const float* __restrict__ g1, const float* __restrict__ b1,
                           const float* __restrict__ wo, const float* __restrict__ w1,
                           const float* __restrict__ b1v, const float* __restrict__ w2,
                           const float* __restrict__ b2v, const float* __restrict__ g2,
                           const float* __restrict__ bb2, const float* __restrict__ gf,
                           const float* __restrict__ bfv, const float* __restrict__ wh) {
    int e = blockIdx.x * blockDim.x + threadIdx.x;

    // ---- stage epilogue weights (padded layout) ----
    if (e < 288) {
        int s = e; float val = 0.f;
        if (s < 48)       { int r = s >> 3, c = s & 7;                 if (c < 6)  val = wo[r * 6 + c]; }
        else if (s < 96)  { int s2 = s - 48;  int r = s2 >> 3, c = s2 & 7;  if (c < 6)  val = w1[r * 6 + c]; }
        else if (s < 144) { int s2 = s - 96;  int r = s2 >> 3, c = s2 & 7;  if (c < 6)  val = w2[r * 6 + c]; }
        else if (s < 240) { int s2 = s - 144; int r = s2 >> 4, c = s2 & 15; if (c < 14) val = wh[r * 14 + c]; }
        else if (s < 248) { int c = s - 240; if (c < 6) val = b1v[c]; }
        else if (s < 256) { int c = s - 248; if (c < 6) val = b2v[c]; }
        else if (s < 264) { int c = s - 256; if (c < 6) val = g2[c]; }
        else if (s < 272) { int c = s - 264; if (c < 6) val = bb2[c]; }
        else if (s < 280) { int c = s - 272; if (c < 6) val = gf[c]; }
        else              { int c = s - 280; if (c < 6) val = bfv[c]; }
        g_sw[s] = val;
    }

    if (e >= NE) return;
    int t = e / NTOK, c = e % NTOK;
    float x[6];
    x[0] = tok_emb[c * 3 + 0]; x[1] = tok_emb[c * 3 + 1]; x[2] = tok_emb[c * 3 + 2];
    x[3] = pos_enc[t * 3 + 0]; x[4] = pos_enc[t * 3 + 1]; x[5] = pos_enc[t * 3 + 2];
    float s = 0.f;
#pragma unroll
    for (int i = 0; i < 6; i++) s += x[i];
    float mu = s * (1.f / 6.f);
    float v = 0.f;
#pragma unroll
    for (int i = 0; i < 6; i++) { float d = x[i] - mu; v += d * d; }
    v *= (1.f / 6.f);
    float r = frsq(v + 1e-5f);
    float n[6];
#pragma unroll
    for (int i = 0; i < 6; i++) n[i] = (x[i] - mu) * r * g1[i] + b1[i];

    float q[6], k[6], vv[6];  // index = h*3+d
#pragma unroll
    for (int j = 0; j < 6; j++) {
        q[j]  = n[3] * wq[j] + n[4] * wq[6 + j] + n[5] * wq[12 + j];
        k[j]  = n[3] * wk[j] + n[4] * wk[6 + j] + n[5] * wk[12 + j];
        vv[j] = n[0] * wv[j] + n[1] * wv[6 + j] + n[2] * wv[12 + j];
    }
    // fold 1/sqrt(HEAD_DIM) and log2(e) into q (inner loop uses ex2)
    const float qs = 1.4426950408889634f * 0.57735026918962576f;
    float2* qp = g_q + e * 3;
#pragma unroll
    for (int d = 0; d < 3; d++) qp[d] = make_float2(q[d] * qs, q[3 + d] * qs);

    u32 w[6];
#pragma unroll
    for (int d = 0; d < 3; d++) {
        w[d]     = ((u32)bfb(k[3 + d])  << 16) | (u32)bfb(k[d]);
        w[3 + d] = ((u32)bfb(vv[3 + d]) << 16) | (u32)bfb(vv[d]);
    }
    u64* kvp = g_kv + e * 5;
    kvp[0] = ((u64)w[1] << 32) | w[0];
    kvp[1] = ((u64)w[3] << 32) | w[2];
    kvp[2] = ((u64)w[5] << 32) | w[4];
    kvp[3] = 0;
    kvp[4] = 0;

    float2* xp = g_x + e * 3;
    xp[0] = make_float2(x[0], x[1]);
    xp[1] = make_float2(x[2], x[3]);
    xp[2] = make_float2(x[4], x[5]);
}

// ---------- per-token layernorm over 6 dims, gamma/beta from const memory ----------
template<int GO, int BO>
__device__ __forceinline__ void ln6c(const float* x, float* o) {
    float s = 0.f;
#pragma unroll
    for (int i = 0; i < 6; i++) s += x[i];
    float mu = s * (1.f / 6.f);
    float v = 0.f;
#pragma unroll
    for (int i = 0; i < 6; i++) { float d = x[i] - mu; v += d * d; }
    v *= (1.f / 6.f);
    float r = frsq(v + 1e-5f);
#pragma unroll
    for (int i = 0; i < 6; i++) o[i] = (x[i] - mu) * r * c_sw[GO + i] + c_sw[BO + i];
}

// branchless GELU via Abramowitz&Stegun 7.1.25 erf (|err| <= 2.5e-5 abs)
__device__ __forceinline__ float gelu_fast(float x) {
    float ax = fabsf(x);
    float z  = ax * 0.70710678118654752f;
    float t  = frcp(fmaf(0.47047f, z, 1.f));
    float poly = t * fmaf(t, fmaf(t, 0.7478556f, -0.0958798f), 0.3480242f);
    float ev = fex2(z * z * -1.4426950408889634f);   // exp(-z^2)
    float E  = fmaf(-poly, ev, 1.f);                  // erf(z), z>=0
    return fmaf(0.5f * ax, E, 0.5f * x);
}

// ---------- per-token epilogue: all weights via const port (no LDS traffic) ----------
__device__ __forceinline__ void epi_token(const float* __restrict__ o,
                                          const float2* __restrict__ xr,
                                          float* __restrict__ outp) {
    // residual + attention out projection
    u64 x1[3] = { pk2f(xr[0]), pk2f(xr[1]), pk2f(xr[2]) };
#pragma unroll
    for (int j = 0; j < 6; j++) {
        u64 oa = rep2(o[j]);
        x1[0] = fma2(oa, cld(j * 8 + 0), x1[0]);
        x1[1] = fma2(oa, cld(j * 8 + 2), x1[1]);
        x1[2] = fma2(oa, cld(j * 8 + 4), x1[2]);
    }
    float xa[6];
#pragma unroll
    for (int p = 0; p < 3; p++) { float2 f = upk2(x1[p]); xa[2 * p] = f.x; xa[2 * p + 1] = f.y; }

    float ha[6];
    ln6c<256, 264>(xa, ha);

    u64 ff[3] = { cld(240), cld(242), cld(244) };
#pragma unroll
    for (int i = 0; i < 6; i++) {
        u64 va = rep2(ha[i]);
        ff[0] = fma2(va, cld(48 + i * 8 + 0), ff[0]);
        ff[1] = fma2(va, cld(48 + i * 8 + 2), ff[1]);
        ff[2] = fma2(va, cld(48 + i * 8 + 4), ff[2]);
    }
    float g[6];
#pragma unroll
    for (int p = 0; p < 3; p++) {
        float2 f = upk2(ff[p]);
        g[2 * p] = gelu_fast(f.x); g[2 * p + 1] = gelu_fast(f.y);
    }
    u64 x2[3];
#pragma unroll
    for (int p = 0; p < 3; p++) x2[p] = add2(x1[p], cld(248 + 2 * p));
#pragma unroll
    for (int j = 0; j < 6; j++) {
        u64 va = rep2(g[j]);
        x2[0] = fma2(va, cld(96 + j * 8 + 0), x2[0]);
        x2[1] = fma2(va, cld(96 + j * 8 + 2), x2[1]);
        x2[2] = fma2(va, cld(96 + j * 8 + 4), x2[2]);
    }
    float ta[6], ya[6];
#pragma unroll
    for (int p = 0; p < 3; p++) { float2 f = upk2(x2[p]); ta[2 * p] = f.x; ta[2 * p + 1] = f.y; }
    ln6c<272, 280>(ta, ya);

    u64 la[7] = {0, 0, 0, 0, 0, 0, 0};
#pragma unroll
    for (int i = 0; i < 6; i++) {
        u64 va = rep2(ya[i]);
#pragma unroll
        for (int p = 0; p < 7; p++) la[p] = fma2(va, cld(144 + i * 16 + 2 * p), la[p]);
    }
    u64* op = (u64*)outp;
#pragma unroll
    for (int p = 0; p < 7; p++) op[p] = la[p];
}

// ---------- attention inner body (shared across main/tail loops) ----------
#define ATT_BODY(KP)                                                              \
    {                                                                             \
        u64 kv0 = (KP)[0], kv1 = (KP)[1], kv2 = (KP)[2];                          \
        u64 K0 = bfpair((u32)kv0), K1 = bfpair((u32)(kv0 >> 32));                 \
        u64 K2 = bfpair((u32)kv1), V0 = bfpair((u32)(kv1 >> 32));                 \
        u64 V1 = bfpair((u32)kv2), V2 = bfpair((u32)(kv2 >> 32));                 \
        u64 s = fma2(q[0], K0, fma2(q[1], K1, mul2(q[2], K2)));                   \
        float2 sf = upk2(s);                                                      \
        u64 w = pk2(fex2(sf.x), fex2(sf.y));                                      \
        den = add2(den, w);                                                       \
        acc[0] = fma2(w, V0, acc[0]);                                             \
        acc[1] = fma2(w, V1, acc[1]);                                             \
        acc[2] = fma2(w, V2, acc[2]);                                             \
    }

// ---------- ONE token end-to-end ----------
__device__ __forceinline__ void attn_one(int t, int lane, int seq,
                                         const float2* __restrict__ sh_q,
                                         const u64* __restrict__ sh_kv,
                                         const float2* __restrict__ sh_x,
                                         const u32* __restrict__ sh_c,
                                         float* __restrict__ out) {
    const u32* cws = sh_c + lane * 9;           // 9 packed-u8 words, stride 9 => conflict-free
    int e = t * NTOK + ((cws[t >> 2] >> ((t & 3) * 8)) & 255);

    u64 q[3];
    {
        const float2* p = sh_q + e * 3;
        q[0] = pk2f(p[0]); q[1] = pk2f(p[1]); q[2] = pk2f(p[2]);
    }

    u64 acc[3] = {0, 0, 0};
    u64 den = 0;   // packed (0.f,0.f)

    const char* kvb = (const char*)sh_kv;
    int n = t + 1;
    int k = 0;
    for (; k + 4 <= n; k += 4) {                 // unrolled by 4, c's from one register
        u32 cw = cws[k >> 2];
        const char* kb = kvb + k * (NTOK * 40);
#pragma unroll
        for (int j = 0; j < 4; j++) {
            int c = (cw >> (8 * j)) & 255;
            const u64* kp = (const u64*)(kb + j * (NTOK * 40) + c * 40);
            ATT_BODY(kp)
        }
    }
    if (k < n) {                                  // <=3 tail iterations, same c-word
        u32 cw = cws[k >> 2];
        for (; k < n; k++) {
            int c = (cw >> (8 * (k & 3))) & 255;
            const u64* kp = (const u64*)(kvb + k * (NTOK * 40) + c * 40);
            ATT_BODY(kp)
        }
    }

    float o[6];   // [h*3+d]
    {
        float2 d = upk2(den); float r0 = frcp(d.x), r1 = frcp(d.y);
#pragma unroll
        for (int j = 0; j < 3; j++) { float2 a = upk2(acc[j]); o[j] = a.x * r0; o[3 + j] = a.y * r1; }
    }

    epi_token(o, sh_x + e * 3, out + (seq * 34 + t) * 14);
}

// ---------- main kernel: 32 sequences/block, 17 warps, warp y does t=y then t=33-y ----------
__global__ void __launch_bounds__(544, 2)
tf_main(const int* __restrict__ idx, float* __restrict__ out) {
    __shared__ float2 sh_q[NE * 3];
    __shared__ u64    sh_kv[NE * 5];
    __shared__ float2 sh_x[NE * 3];
    __shared__ u32    sh_c[32 * 9];   // packed u8 token-ids: lane-major, 9 words/lane

    const int NT = 544;
    int tid = threadIdx.y * 32 + threadIdx.x;
    int base = blockIdx.x * 32;

    for (int i = tid; i < NE * 3; i += NT) {
        sh_q[i] = g_q[i];
        sh_x[i] = g_x[i];
    }
    for (int i = tid; i < NE * 5; i += NT) sh_kv[i] = g_kv[i];
    for (int i = tid; i < 32 * 9; i += NT) {
        int ln = i / 9, kg = i % 9;
        u32 w = 0;
        int kb = kg * 4;
#pragma unroll
        for (int j = 0; j < 4; j++) {
            int k = kb + j;
            if (k < T_SEQ) w |= ((u32)idx[(base + ln) * T_SEQ + k]) << (8 * j);
        }
        sh_c[ln * 9 + kg] = w;
    }
    __syncthreads();

    int lane = threadIdx.x, y = threadIdx.y;
    int seq = base + lane;

    attn_one(y, lane, seq, sh_q, sh_kv, sh_x, sh_c, out);
    __syncwarp();   // keep token-2 state out of token-1's live range
    attn_one(33 - y, lane, seq, sh_q, sh_kv, sh_x, sh_c, out);
}

extern "C" void kernel_launch(void* const* d_in, const int* in_sizes, int n_in,
                              void* d_out, int out_size) {
    const int*   idx     = (const int*)d_in[0];
    const float* tok_emb = (const float*)d_in[1];
    const float* pos_enc = (const float*)d_in[2];
    const float* wq      = (const float*)d_in[3];
    const float* wk      = (const float*)d_in[4];
    const float* wv      = (const float*)d_in[5];
    const float* wo      = (const float*)d_in[6];
    const float* ln1_g   = (const float*)d_in[7];
    const float* ln1_b   = (const float*)d_in[8];
    const float* ln2_g   = (const float*)d_in[9];
    const float* ln2_b   = (const float*)d_in[10];
    const float* w1      = (const float*)d_in[11];
    const float* b1      = (const float*)d_in[12];
    const float* w2      = (const float*)d_in[13];
    const float* b2      = (const float*)d_in[14];
    const float* lnf_g   = (const float*)d_in[15];
    const float* lnf_b   = (const float*)d_in[16];
    const float* wh      = (const float*)d_in[17];

    int nseq = in_sizes[0] / T_SEQ;

    build_luts<<<1, 512>>>(tok_emb, pos_enc, wq, wk, wv, ln1_g, ln1_b,
                           wo, w1, b1, w2, b2, ln2_g, ln2_b, lnf_g, lnf_b, wh);

    // copy staged weight block into constant memory (D2D memcpy: graph-capturable)
    void *c_addr = nullptr, *s_addr = nullptr;
    cudaGetSymbolAddress(&c_addr, c_sw);
    cudaGetSymbolAddress(&s_addr, g_sw);
    cudaMemcpyAsync(c_addr, s_addr, 288 * sizeof(float), cudaMemcpyDeviceToDevice);

    dim3 blk(32, 17);
    tf_main<<<nseq / 32, blk>>>(idx, (float*)d_out);
}

// round 15
// speedup vs baseline: 1.0185x; 1.0185x over previous
#include <cuda_runtime.h>
#include <cuda_bf16.h>

#define T_SEQ 34
#define NTOK  14
#define NE    476   // 34*14 distinct (position, token) variants

typedef unsigned long long u64;
typedef unsigned int       u32;

// LUTs built by prologue kernel (device globals: no allocation allowed)
__device__ float2 g_q[NE * 3];   // prescaled q, packed (head0, head1) per dim
__device__ u64    g_kv[NE * 5];  // 40B/entry: [0]=K01 bf16x4, [1].lo=K2 bf16x2, [2..4]=V f32x2
__device__ float2 g_x[NE * 3];   // raw embedded x (pre-LN), for residual
__device__ float  g_sw[288];     // staged epilogue weights (padded layout)

// epilogue weights in constant memory: uniform loads via const port
__constant__ __align__(16) float c_sw[288];

// ---------- packed f32x2 helpers (sm_103a) ----------
__device__ __forceinline__ u64 pk2(float a, float b) {
    u64 r; asm("mov.b64 %0,{%1,%2};" : "=l"(r) : "f"(a), "f"(b)); return r;
}
__device__ __forceinline__ u64 pk2f(float2 f) { return pk2(f.x, f.y); }
__device__ __forceinline__ float2 upk2(u64 v) {
    float2 f; asm("mov.b64 {%0,%1},%2;" : "=f"(f.x), "=f"(f.y) : "l"(v)); return f;
}
__device__ __forceinline__ u64 rep2(float a) {
    u64 r; asm("mov.b64 %0,{%1,%1};" : "=l"(r) : "f"(a)); return r;
}
__device__ __forceinline__ u64 fma2(u64 a, u64 b, u64 c) {
    u64 d; asm("fma.rn.f32x2 %0,%1,%2,%3;" : "=l"(d) : "l"(a), "l"(b), "l"(c)); return d;
}
__device__ __forceinline__ u64 add2(u64 a, u64 b) {
    u64 d; asm("add.rn.f32x2 %0,%1,%2;" : "=l"(d) : "l"(a), "l"(b)); return d;
}
__device__ __forceinline__ u64 mul2(u64 a, u64 b) {
    u64 d; asm("mul.rn.f32x2 %0,%1,%2;" : "=l"(d) : "l"(a), "l"(b)); return d;
}
// bf16x2 (lo=head0, hi=head1) -> f32x2
__device__ __forceinline__ u64 bfpair(u32 u) {
    u32 lo = u << 16, hi = u & 0xffff0000u;
    u64 r; asm("mov.b64 %0,{%1,%2};" : "=l"(r) : "r"(lo), "r"(hi)); return r;
}
__device__ __forceinline__ float fex2(float x) { float r; asm("ex2.approx.f32 %0,%1;" : "=f"(r) : "f"(x)); return r; }
__device__ __forceinline__ float frcp(float x) { float r; asm("rcp.approx.f32 %0,%1;" : "=f"(r) : "f"(x)); return r; }
__device__ __forceinline__ float frsq(float x) { float r; asm("rsqrt.approx.f32 %0,%1;" : "=f"(r) : "f"(x)); return r; }

__device__ __forceinline__ unsigned short bfb(float f) {
    return __bfloat16_as_ushort(__float2bfloat16_rn(f));
}

// const-space u64 fetch (off = float index, must be even)
__device__ __forceinline__ u64 cld(int off) {
    return *reinterpret_cast<const u64*>(c_sw + off);
}

// ---------- prologue: build 476-entry LUTs + stage epilogue weight block ----------
__global__ void build_luts(const float* __restrict__ tok_emb, const float* __restrict__ pos_enc,
                           const float* __restrict__ wq, const float* __restrict__ wk,
                           const float* __restrict__ wv,
                           const float* __restrict__ g1, const float* __restrict__ b1,
                           const float* __restrict__ wo, const float* __restrict__ w1,
                           const float* __restrict__ b1v, const float* __restrict__ w2,
                           const float* __restrict__ b2v, const float* __restrict__ g2,
                           const float* __restrict__ bb2, const float* __restrict__ gf,
                           const float* __restrict__ bfv, const float* __restrict__ wh) {
    int e = blockIdx.x * blockDim.x + threadIdx.x;

    // ---- stage epilogue weights (padded layout) ----
    if (e < 288) {
        int s = e; float val = 0.f;
        if (s < 48)       { int r = s >> 3, c = s & 7;                 if (c < 6)  val = wo[r * 6 + c]; }
        else if (s < 96)  { int s2 = s - 48;  int r = s2 >> 3, c = s2 & 7;  if (c < 6)  val = w1[r * 6 + c]; }
        else if (s < 144) { int s2 = s - 96;  int r = s2 >> 3, c = s2 & 7;  if (c < 6)  val = w2[r * 6 + c]; }
        else if (s < 240) { int s2 = s - 144; int r = s2 >> 4, c = s2 & 15; if (c < 14) val = wh[r * 14 + c]; }
        else if (s < 248) { int c = s - 240; if (c < 6) val = b1v[c]; }
        else if (s < 256) { int c = s - 248; if (c < 6) val = b2v[c]; }
        else if (s < 264) { int c = s - 256; if (c < 6) val = g2[c]; }
        else if (s < 272) { int c = s - 264; if (c < 6) val = bb2[c]; }
        else if (s < 280) { int c = s - 272; if (c < 6) val = gf[c]; }
        else              { int c = s - 280; if (c < 6) val = bfv[c]; }
        g_sw[s] = val;
    }

    if (e >= NE) return;
    int t = e / NTOK, c = e % NTOK;
    float x[6];
    x[0] = tok_emb[c * 3 + 0]; x[1] = tok_emb[c * 3 + 1]; x[2] = tok_emb[c * 3 + 2];
    x[3] = pos_enc[t * 3 + 0]; x[4] = pos_enc[t * 3 + 1]; x[5] = pos_enc[t * 3 + 2];
    float s = 0.f;
#pragma unroll
    for (int i = 0; i < 6; i++) s += x[i];
    float mu = s * (1.f / 6.f);
    float v = 0.f;
#pragma unroll
    for (int i = 0; i < 6; i++) { float d = x[i] - mu; v += d * d; }
    v *= (1.f / 6.f);
    float r = frsq(v + 1e-5f);
    float n[6];
#pragma unroll
    for (int i = 0; i < 6; i++) n[i] = (x[i] - mu) * r * g1[i] + b1[i];

    float q[6], k[6], vv[6];  // index = h*3+d
#pragma unroll
    for (int j = 0; j < 6; j++) {
        q[j]  = n[3] * wq[j] + n[4] * wq[6 + j] + n[5] * wq[12 + j];
        k[j]  = n[3] * wk[j] + n[4] * wk[6 + j] + n[5] * wk[12 + j];
        vv[j] = n[0] * wv[j] + n[1] * wv[6 + j] + n[2] * wv[12 + j];
    }
    // fold 1/sqrt(HEAD_DIM) and log2(e) into q (inner loop uses ex2)
    const float qs = 1.4426950408889634f * 0.57735026918962576f;
    float2* qp = g_q + e * 3;
#pragma unroll
    for (int d = 0; d < 3; d++) qp[d] = make_float2(q[d] * qs, q[3 + d] * qs);

    // K as bf16 pairs (d0,d1 in one u64; d2 in lo32 of next), V as f32x2 (exact)
    u32 kw[3];
#pragma unroll
    for (int d = 0; d < 3; d++)
        kw[d] = ((u32)bfb(k[3 + d]) << 16) | (u32)bfb(k[d]);
    u64* kvp = g_kv + e * 5;
    kvp[0] = ((u64)kw[1] << 32) | kw[0];
    kvp[1] = (u64)kw[2];
    kvp[2] = ((u64)__float_as_uint(vv[3]) << 32) | __float_as_uint(vv[0]);
    kvp[3] = ((u64)__float_as_uint(vv[4]) << 32) | __float_as_uint(vv[1]);
    kvp[4] = ((u64)__float_as_uint(vv[5]) << 32) | __float_as_uint(vv[2]);

    float2* xp = g_x + e * 3;
    xp[0] = make_float2(x[0], x[1]);
    xp[1] = make_float2(x[2], x[3]);
    xp[2] = make_float2(x[4], x[5]);
}

// ---------- per-token layernorm over 6 dims, gamma/beta from const memory ----------
template<int GO, int BO>
__device__ __forceinline__ void ln6c(const float* x, float* o) {
    float s = 0.f;
#pragma unroll
    for (int i = 0; i < 6; i++) s += x[i];
    float mu = s * (1.f / 6.f);
    float v = 0.f;
#pragma unroll
    for (int i = 0; i < 6; i++) { float d = x[i] - mu; v += d * d; }
    v *= (1.f / 6.f);
    float r = frsq(v + 1e-5f);
#pragma unroll
    for (int i = 0; i < 6; i++) o[i] = (x[i] - mu) * r * c_sw[GO + i] + c_sw[BO + i];
}

// branchless GELU via Abramowitz&Stegun 7.1.25 erf (|err| <= 2.5e-5 abs)
__device__ __forceinline__ float gelu_fast(float x) {
    float ax = fabsf(x);
    float z  = ax * 0.70710678118654752f;
    float t  = frcp(fmaf(0.47047f, z, 1.f));
    float poly = t * fmaf(t, fmaf(t, 0.7478556f, -0.0958798f), 0.3480242f);
    float ev = fex2(z * z * -1.4426950408889634f);   // exp(-z^2)
    float E  = fmaf(-poly, ev, 1.f);                  // erf(z), z>=0
    return fmaf(0.5f * ax, E, 0.5f * x);
}

// ---------- per-token epilogue: all weights via const port (no LDS traffic) ----------
__device__ __forceinline__ void epi_token(const float* __restrict__ o,
                                          const float2* __restrict__ xr,
                                          float* __restrict__ outp) {
    // residual + attention out projection
    u64 x1[3] = { pk2f(xr[0]), pk2f(xr[1]), pk2f(xr[2]) };
#pragma unroll
    for (int j = 0; j < 6; j++) {
        u64 oa = rep2(o[j]);
        x1[0] = fma2(oa, cld(j * 8 + 0), x1[0]);
        x1[1] = fma2(oa, cld(j * 8 + 2), x1[1]);
        x1[2] = fma2(oa, cld(j * 8 + 4), x1[2]);
    }
    float xa[6];
#pragma unroll
    for (int p = 0; p < 3; p++) { float2 f = upk2(x1[p]); xa[2 * p] = f.x; xa[2 * p + 1] = f.y; }

    float ha[6];
    ln6c<256, 264>(xa, ha);

    u64 ff[3] = { cld(240), cld(242), cld(244) };
#pragma unroll
    for (int i = 0; i < 6; i++) {
        u64 va = rep2(ha[i]);
        ff[0] = fma2(va, cld(48 + i * 8 + 0), ff[0]);
        ff[1] = fma2(va, cld(48 + i * 8 + 2), ff[1]);
        ff[2] = fma2(va, cld(48 + i * 8 + 4), ff[2]);
    }
    float g[6];
#pragma unroll
    for (int p = 0; p < 3; p++) {
        float2 f = upk2(ff[p]);
        g[2 * p] = gelu_fast(f.x); g[2 * p + 1] = gelu_fast(f.y);
    }
    u64 x2[3];
#pragma unroll
    for (int p = 0; p < 3; p++) x2[p] = add2(x1[p], cld(248 + 2 * p));
#pragma unroll
    for (int j = 0; j < 6; j++) {
        u64 va = rep2(g[j]);
        x2[0] = fma2(va, cld(96 + j * 8 + 0), x2[0]);
        x2[1] = fma2(va, cld(96 + j * 8 + 2), x2[1]);
        x2[2] = fma2(va, cld(96 + j * 8 + 4), x2[2]);
    }
    float ta[6], ya[6];
#pragma unroll
    for (int p = 0; p < 3; p++) { float2 f = upk2(x2[p]); ta[2 * p] = f.x; ta[2 * p + 1] = f.y; }
    ln6c<272, 280>(ta, ya);

    u64 la[7] = {0, 0, 0, 0, 0, 0, 0};
#pragma unroll
    for (int i = 0; i < 6; i++) {
        u64 va = rep2(ya[i]);
#pragma unroll
        for (int p = 0; p < 7; p++) la[p] = fma2(va, cld(144 + i * 16 + 2 * p), la[p]);
    }
    u64* op = (u64*)outp;
#pragma unroll
    for (int p = 0; p < 7; p++) op[p] = la[p];
}

// ---------- attention inner body: K bf16 (3 unpacks), V f32x2 direct ----------
#define ATT_BODY(KP)                                                              \
    {                                                                             \
        u64 k01 = (KP)[0];                                                        \
        u32 k2w = *(const u32*)((const char*)(KP) + 8);                           \
        u64 K0 = bfpair((u32)k01), K1 = bfpair((u32)(k01 >> 32));                 \
        u64 K2 = bfpair(k2w);                                                     \
        u64 V0 = (KP)[2], V1 = (KP)[3], V2 = (KP)[4];                             \
        u64 s = fma2(q[0], K0, fma2(q[1], K1, mul2(q[2], K2)));                   \
        float2 sf = upk2(s);                                                      \
        u64 w = pk2(fex2(sf.x), fex2(sf.y));                                      \
        den = add2(den, w);                                                       \
        acc[0] = fma2(w, V0, acc[0]);                                             \
        acc[1] = fma2(w, V1, acc[1]);                                             \
        acc[2] = fma2(w, V2, acc[2]);                                             \
    }

// ---------- ONE token end-to-end ----------
__device__ __forceinline__ void attn_one(int t, int lane, int seq,
                                         const float2* __restrict__ sh_q,
                                         const u64* __restrict__ sh_kv,
                                         const float2* __restrict__ sh_x,
                                         const u32* __restrict__ sh_c,
                                         float* __restrict__ out) {
    const u32* cws = sh_c + lane * 9;           // 9 packed-u8 words, stride 9 => conflict-free
    int e = t * NTOK + ((cws[t >> 2] >> ((t & 3) * 8)) & 255);

    u64 q[3];
    {
        const float2* p = sh_q + e * 3;
        q[0] = pk2f(p[0]); q[1] = pk2f(p[1]); q[2] = pk2f(p[2]);
    }

    u64 acc[3] = {0, 0, 0};
    u64 den = 0;   // packed (0.f,0.f)

    const char* kvb = (const char*)sh_kv;
    int n = t + 1;
    int k = 0;
    for (; k + 4 <= n; k += 4) {                 // unrolled by 4, c's from one register
        u32 cw = cws[k >> 2];
        const char* kb = kvb + k * (NTOK * 40);
#pragma unroll
        for (int j = 0; j < 4; j++) {
            int c = (cw >> (8 * j)) & 255;
            const u64* kp = (const u64*)(kb + j * (NTOK * 40) + c * 40);
            ATT_BODY(kp)
        }
    }
    if (k < n) {                                  // <=3 tail iterations, same c-word
        u32 cw = cws[k >> 2];
        for (; k < n; k++) {
            int c = (cw >> (8 * (k & 3))) & 255;
            const u64* kp = (const u64*)(kvb + k * (NTOK * 40) + c * 40);
            ATT_BODY(kp)
        }
    }

    float o[6];   // [h*3+d]
    {
        float2 d = upk2(den); float r0 = frcp(d.x), r1 = frcp(d.y);
#pragma unroll
        for (int j = 0; j < 3; j++) { float2 a = upk2(acc[j]); o[j] = a.x * r0; o[3 + j] = a.y * r1; }
    }

    epi_token(o, sh_x + e * 3, out + (seq * 34 + t) * 14);
}

// ---------- main kernel: 32 sequences/block, 17 warps, warp y does t=y then t=33-y ----------
__global__ void __launch_bounds__(544, 2)
tf_main(const int* __restrict__ idx, float* __restrict__ out) {
    __shared__ float2 sh_q[NE * 3];
    __shared__ u64    sh_kv[NE * 5];
    __shared__ float2 sh_x[NE * 3];
    __shared__ u32    sh_c[32 * 9];   // packed u8 token-ids: lane-major, 9 words/lane

    const int NT = 544;
    int tid = threadIdx.y * 32 + threadIdx.x;
    int base = blockIdx.x * 32;

    for (int i = tid; i < NE * 3; i += NT) {
        sh_q[i] = g_q[i];
        sh_x[i] = g_x[i];
    }
    for (int i = tid; i < NE * 5; i += NT) sh_kv[i] = g_kv[i];
    for (int i = tid; i < 32 * 9; i += NT) {
        int ln = i / 9, kg = i % 9;
        u32 w = 0;
        int kb = kg * 4;
#pragma unroll
        for (int j = 0; j < 4; j++) {
            int k = kb + j;
            if (k < T_SEQ) w |= ((u32)idx[(base + ln) * T_SEQ + k]) << (8 * j);
        }
        sh_c[ln * 9 + kg] = w;
    }
    __syncthreads();

    int lane = threadIdx.x, y = threadIdx.y;
    int seq = base + lane;

    attn_one(y, lane, seq, sh_q, sh_kv, sh_x, sh_c, out);
    __syncwarp();   // keep token-2 state out of token-1's live range
    attn_one(33 - y, lane, seq, sh_q, sh_kv, sh_x, sh_c, out);
}

extern "C" void kernel_launch(void* const* d_in, const int* in_sizes, int n_in,
                              void* d_out, int out_size) {
    const int*   idx     = (const int*)d_in[0];
    const float* tok_emb = (const float*)d_in[1];
    const float* pos_enc = (const float*)d_in[2];
    const float* wq      = (const float*)d_in[3];
    const float* wk      = (const float*)d_in[4];
    const float* wv      = (const float*)d_in[5];
    const float* wo      = (const float*)d_in[6];
    const float* ln1_g   = (const float*)d_in[7];
    const float* ln1_b   = (const float*)d_in[8];
    const float* ln2_g   = (const float*)d_in[9];
    const float* ln2_b   = (const float*)d_in[10];
    const float* w1      = (const float*)d_in[11];
    const float* b1      = (const float*)d_in[12];
    const float* w2      = (const float*)d_in[13];
    const float* b2      = (const float*)d_in[14];
    const float* lnf_g   = (const float*)d_in[15];
    const float* lnf_b   = (const float*)d_in[16];
    const float* wh      = (const float*)d_in[17];

    int nseq = in_sizes[0] / T_SEQ;

    build_luts<<<1, 512>>>(tok_emb, pos_enc, wq, wk, wv, ln1_g, ln1_b,
                           wo, w1, b1, w2, b2, ln2_g, ln2_b, lnf_g, lnf_b, wh);

    // copy staged weight block into constant memory (D2D memcpy: graph-capturable)
    void *c_addr = nullptr, *s_addr = nullptr;
    cudaGetSymbolAddress(&c_addr, c_sw);
    cudaGetSymbolAddress(&s_addr, g_sw);
    cudaMemcpyAsync(c_addr, s_addr, 288 * sizeof(float), cudaMemcpyDeviceToDevice);

    dim3 blk(32, 17);
    tf_main<<<nseq / 32, blk>>>(idx, (float*)d_out);
}

// round 16
// speedup vs baseline: 1.0713x; 1.0519x over previous
#include <cuda_runtime.h>
#include <cuda_bf16.h>

#define T_SEQ 34
#define NTOK  14
#define NE    476   // 34*14 distinct (position, token) variants

typedef unsigned long long u64;
typedef unsigned int       u32;

// LUTs built by prologue kernel (device globals: no allocation allowed)
__device__ u32    g_qb[NE * 3];  // prescaled q as bf16x2 (lo=head0, hi=head1) per dim
__device__ u64    g_kv[NE * 5];  // 40B/entry: [0]=K01 bf16x2 pairs, [1].lo=K2, [2..4]=V f32x2
__device__ float2 g_x[NE * 3];   // raw embedded x (pre-LN), for residual
__device__ float  g_sw[288];     // staged epilogue weights (padded layout)

// epilogue weights in constant memory: uniform loads via const port
__constant__ __align__(16) float c_sw[288];

// ---------- packed f32x2 helpers (sm_103a) ----------
__device__ __forceinline__ u64 pk2(float a, float b) {
    u64 r; asm("mov.b64 %0,{%1,%2};" : "=l"(r) : "f"(a), "f"(b)); return r;
}
__device__ __forceinline__ u64 pk2f(float2 f) { return pk2(f.x, f.y); }
__device__ __forceinline__ float2 upk2(u64 v) {
    float2 f; asm("mov.b64 {%0,%1},%2;" : "=f"(f.x), "=f"(f.y) : "l"(v)); return f;
}
__device__ __forceinline__ u64 rep2(float a) {
    u64 r; asm("mov.b64 %0,{%1,%1};" : "=l"(r) : "f"(a)); return r;
}
__device__ __forceinline__ u64 fma2(u64 a, u64 b, u64 c) {
    u64 d; asm("fma.rn.f32x2 %0,%1,%2,%3;" : "=l"(d) : "l"(a), "l"(b), "l"(c)); return d;
}
__device__ __forceinline__ u64 add2(u64 a, u64 b) {
    u64 d; asm("add.rn.f32x2 %0,%1,%2;" : "=l"(d) : "l"(a), "l"(b)); return d;
}
__device__ __forceinline__ u64 mul2(u64 a, u64 b) {
    u64 d; asm("mul.rn.f32x2 %0,%1,%2;" : "=l"(d) : "l"(a), "l"(b)); return d;
}
// packed bf16x2 math (both heads per register)
__device__ __forceinline__ u32 hfma2b(u32 a, u32 b, u32 c) {
    u32 d; asm("fma.rn.bf16x2 %0,%1,%2,%3;" : "=r"(d) : "r"(a), "r"(b), "r"(c)); return d;
}
__device__ __forceinline__ u32 hmul2b(u32 a, u32 b) {
    u32 d; asm("mul.bf16x2 %0,%1,%2;" : "=r"(d) : "r"(a), "r"(b)); return d;
}
__device__ __forceinline__ float fex2(float x) { float r; asm("ex2.approx.f32 %0,%1;" : "=f"(r) : "f"(x)); return r; }
__device__ __forceinline__ float frcp(float x) { float r; asm("rcp.approx.f32 %0,%1;" : "=f"(r) : "f"(x)); return r; }
__device__ __forceinline__ float frsq(float x) { float r; asm("rsqrt.approx.f32 %0,%1;" : "=f"(r) : "f"(x)); return r; }

__device__ __forceinline__ unsigned short bfb(float f) {
    return __bfloat16_as_ushort(__float2bfloat16_rn(f));
}

// const-space u64 fetch (off = float index, must be even)
__device__ __forceinline__ u64 cld(int off) {
    return *reinterpret_cast<const u64*>(c_sw + off);
}

// ---------- prologue: build 476-entry LUTs + stage epilogue weight block ----------
__global__ void build_luts(const float* __restrict__ tok_emb, const float* __restrict__ pos_enc,
                           const float* __restrict__ wq, const float* __restrict__ wk,
                           const float* __restrict__ wv,
                           const float* __restrict__ g1, const float* __restrict__ b1,
                           const float* __restrict__ wo, const float* __restrict__ w1,
                           const float* __restrict__ b1v, const float* __restrict__ w2,
                           const float* __restrict__ b2v, const float* __restrict__ g2,
                           const float* __restrict__ bb2, const float* __restrict__ gf,
                           const float* __restrict__ bfv, const float* __restrict__ wh) {
    int e = blockIdx.x * blockDim.x + threadIdx.x;

    // ---- stage epilogue weights (padded layout) ----
    if (e < 288) {
        int s = e; float val = 0.f;
        if (s < 48)       { int r = s >> 3, c = s & 7;                 if (c < 6)  val = wo[r * 6 + c]; }
        else if (s < 96)  { int s2 = s - 48;  int r = s2 >> 3, c = s2 & 7;  if (c < 6)  val = w1[r * 6 + c]; }
        else if (s < 144) { int s2 = s - 96;  int r = s2 >> 3, c = s2 & 7;  if (c < 6)  val = w2[r * 6 + c]; }
        else if (s < 240) { int s2 = s - 144; int r = s2 >> 4, c = s2 & 15; if (c < 14) val = wh[r * 14 + c]; }
        else if (s < 248) { int c = s - 240; if (c < 6) val = b1v[c]; }
        else if (s < 256) { int c = s - 248; if (c < 6) val = b2v[c]; }
        else if (s < 264) { int c = s - 256; if (c < 6) val = g2[c]; }
        else if (s < 272) { int c = s - 264; if (c < 6) val = bb2[c]; }
        else if (s < 280) { int c = s - 272; if (c < 6) val = gf[c]; }
        else              { int c = s - 280; if (c < 6) val = bfv[c]; }
        g_sw[s] = val;
    }

    if (e >= NE) return;
    int t = e / NTOK, c = e % NTOK;
    float x[6];
    x[0] = tok_emb[c * 3 + 0]; x[1] = tok_emb[c * 3 + 1]; x[2] = tok_emb[c * 3 + 2];
    x[3] = pos_enc[t * 3 + 0]; x[4] = pos_enc[t * 3 + 1]; x[5] = pos_enc[t * 3 + 2];
    float s = 0.f;
#pragma unroll
    for (int i = 0; i < 6; i++) s += x[i];
    float mu = s * (1.f / 6.f);
    float v = 0.f;
#pragma unroll
    for (int i = 0; i < 6; i++) { float d = x[i] - mu; v += d * d; }
    v *= (1.f / 6.f);
    float r = frsq(v + 1e-5f);
    float n[6];
#pragma unroll
    for (int i = 0; i < 6; i++) n[i] = (x[i] - mu) * r * g1[i] + b1[i];

    float q[6], k[6], vv[6];  // index = h*3+d
#pragma unroll
    for (int j = 0; j < 6; j++) {
        q[j]  = n[3] * wq[j] + n[4] * wq[6 + j] + n[5] * wq[12 + j];
        k[j]  = n[3] * wk[j] + n[4] * wk[6 + j] + n[5] * wk[12 + j];
        vv[j] = n[0] * wv[j] + n[1] * wv[6 + j] + n[2] * wv[12 + j];
    }
    // fold 1/sqrt(HEAD_DIM) and log2(e) into q (inner loop uses ex2)
    const float qs = 1.4426950408889634f * 0.57735026918962576f;
#pragma unroll
    for (int d = 0; d < 3; d++)
        g_qb[e * 3 + d] = ((u32)bfb(q[3 + d] * qs) << 16) | (u32)bfb(q[d] * qs);

    // K as bf16x2 (lo=head0, hi=head1) per dim; V as f32x2 (exact)
    u32 kw[3];
#pragma unroll
    for (int d = 0; d < 3; d++)
        kw[d] = ((u32)bfb(k[3 + d]) << 16) | (u32)bfb(k[d]);
    u64* kvp = g_kv + e * 5;
    kvp[0] = ((u64)kw[1] << 32) | kw[0];
    kvp[1] = (u64)kw[2];
    kvp[2] = ((u64)__float_as_uint(vv[3]) << 32) | __float_as_uint(vv[0]);
    kvp[3] = ((u64)__float_as_uint(vv[4]) << 32) | __float_as_uint(vv[1]);
    kvp[4] = ((u64)__float_as_uint(vv[5]) << 32) | __float_as_uint(vv[2]);

    float2* xp = g_x + e * 3;
    xp[0] = make_float2(x[0], x[1]);
    xp[1] = make_float2(x[2], x[3]);
    xp[2] = make_float2(x[4], x[5]);
}

// ---------- per-token layernorm over 6 dims, gamma/beta from const memory ----------
template<int GO, int BO>
__device__ __forceinline__ void ln6c(const float* x, float* o) {
    float s = 0.f;
#pragma unroll
    for (int i = 0; i < 6; i++) s += x[i];
    float mu = s * (1.f / 6.f);
    float v = 0.f;
#pragma unroll
    for (int i = 0; i < 6; i++) { float d = x[i] - mu; v += d * d; }
    v *= (1.f / 6.f);
    float r = frsq(v + 1e-5f);
#pragma unroll
    for (int i = 0; i < 6; i++) o[i] = (x[i] - mu) * r * c_sw[GO + i] + c_sw[BO + i];
}

// branchless GELU via Abramowitz&Stegun 7.1.25 erf (|err| <= 2.5e-5 abs)
__device__ __forceinline__ float gelu_fast(float x) {
    float ax = fabsf(x);
    float z  = ax * 0.70710678118654752f;
    float t  = frcp(fmaf(0.47047f, z, 1.f));
    float poly = t * fmaf(t, fmaf(t, 0.7478556f, -0.0958798f), 0.3480242f);
    float ev = fex2(z * z * -1.4426950408889634f);   // exp(-z^2)
    float E  = fmaf(-poly, ev, 1.f);                  // erf(z), z>=0
    return fmaf(0.5f * ax, E, 0.5f * x);
}

// ---------- per-token epilogue: all weights via const port (no LDS traffic) ----------
__device__ __forceinline__ void epi_token(const float* __restrict__ o,
                                          const float2* __restrict__ xr,
                                          float* __restrict__ outp) {
    // residual + attention out projection
    u64 x1[3] = { pk2f(xr[0]), pk2f(xr[1]), pk2f(xr[2]) };
#pragma unroll
    for (int j = 0; j < 6; j++) {
        u64 oa = rep2(o[j]);
        x1[0] = fma2(oa, cld(j * 8 + 0), x1[0]);
        x1[1] = fma2(oa, cld(j * 8 + 2), x1[1]);
        x1[2] = fma2(oa, cld(j * 8 + 4), x1[2]);
    }
    float xa[6];
#pragma unroll
    for (int p = 0; p < 3; p++) { float2 f = upk2(x1[p]); xa[2 * p] = f.x; xa[2 * p + 1] = f.y; }

    float ha[6];
    ln6c<256, 264>(xa, ha);

    u64 ff[3] = { cld(240), cld(242), cld(244) };
#pragma unroll
    for (int i = 0; i < 6; i++) {
        u64 va = rep2(ha[i]);
        ff[0] = fma2(va, cld(48 + i * 8 + 0), ff[0]);
        ff[1] = fma2(va, cld(48 + i * 8 + 2), ff[1]);
        ff[2] = fma2(va, cld(48 + i * 8 + 4), ff[2]);
    }
    float g[6];
#pragma unroll
    for (int p = 0; p < 3; p++) {
        float2 f = upk2(ff[p]);
        g[2 * p] = gelu_fast(f.x); g[2 * p + 1] = gelu_fast(f.y);
    }
    u64 x2[3];
#pragma unroll
    for (int p = 0; p < 3; p++) x2[p] = add2(x1[p], cld(248 + 2 * p));
#pragma unroll
    for (int j = 0; j < 6; j++) {
        u64 va = rep2(g[j]);
        x2[0] = fma2(va, cld(96 + j * 8 + 0), x2[0]);
        x2[1] = fma2(va, cld(96 + j * 8 + 2), x2[1]);
        x2[2] = fma2(va, cld(96 + j * 8 + 4), x2[2]);
    }
    float ta[6], ya[6];
#pragma unroll
    for (int p = 0; p < 3; p++) { float2 f = upk2(x2[p]); ta[2 * p] = f.x; ta[2 * p + 1] = f.y; }
    ln6c<272, 280>(ta, ya);

    u64 la[7] = {0, 0, 0, 0, 0, 0, 0};
#pragma unroll
    for (int i = 0; i < 6; i++) {
        u64 va = rep2(ya[i]);
#pragma unroll
        for (int p = 0; p < 7; p++) la[p] = fma2(va, cld(144 + i * 16 + 2 * p), la[p]);
    }
    u64* op = (u64*)outp;
#pragma unroll
    for (int p = 0; p < 7; p++) op[p] = la[p];
}

// ---------- attention inner body: bf16x2 dot (no K unpack), V f32x2 direct ----------
#define ATT_BODY(KP)                                                              \
    {                                                                             \
        u64 k01 = (KP)[0];                                                        \
        u32 k2w = *(const u32*)((const char*)(KP) + 8);                           \
        u32 sb = hfma2b(qb0, (u32)k01,                                            \
                 hfma2b(qb1, (u32)(k01 >> 32), hmul2b(qb2, k2w)));                \
        float f0 = __uint_as_float(sb << 16);                                     \
        float f1 = __uint_as_float(sb & 0xffff0000u);                             \
        u64 V0 = (KP)[2], V1 = (KP)[3], V2 = (KP)[4];                             \
        u64 w = pk2(fex2(f0), fex2(f1));                                          \
        den = add2(den, w);                                                       \
        acc[0] = fma2(w, V0, acc[0]);                                             \
        acc[1] = fma2(w, V1, acc[1]);                                             \
        acc[2] = fma2(w, V2, acc[2]);                                             \
    }

// ---------- ONE token end-to-end ----------
__device__ __forceinline__ void attn_one(int t, int lane, int seq,
                                         const u32* __restrict__ sh_qb,
                                         const u64* __restrict__ sh_kv,
                                         const float2* __restrict__ sh_x,
                                         const u32* __restrict__ sh_c,
                                         float* __restrict__ out) {
    const u32* cws = sh_c + lane * 9;           // 9 packed-u8 words, stride 9 => conflict-free
    int e = t * NTOK + ((cws[t >> 2] >> ((t & 3) * 8)) & 255);

    const u32* qp = sh_qb + e * 3;
    u32 qb0 = qp[0], qb1 = qp[1], qb2 = qp[2];

    u64 acc[3] = {0, 0, 0};
    u64 den = 0;   // packed (0.f,0.f)

    const char* kvb = (const char*)sh_kv;
    int n = t + 1;
    int k = 0;
    for (; k + 4 <= n; k += 4) {                 // unrolled by 4, c's from one register
        u32 cw = cws[k >> 2];
        const char* kb = kvb + k * (NTOK * 40);
#pragma unroll
        for (int j = 0; j < 4; j++) {
            int c = (cw >> (8 * j)) & 255;
            const u64* kp = (const u64*)(kb + j * (NTOK * 40) + c * 40);
            ATT_BODY(kp)
        }
    }
    if (k < n) {                                  // <=3 tail iterations, same c-word
        u32 cw = cws[k >> 2];
        for (; k < n; k++) {
            int c = (cw >> (8 * (k & 3))) & 255;
            const u64* kp = (const u64*)(kvb + k * (NTOK * 40) + c * 40);
            ATT_BODY(kp)
        }
    }

    float o[6];   // [h*3+d]
    {
        float2 d = upk2(den); float r0 = frcp(d.x), r1 = frcp(d.y);
#pragma unroll
        for (int j = 0; j < 3; j++) { float2 a = upk2(acc[j]); o[j] = a.x * r0; o[3 + j] = a.y * r1; }
    }

    epi_token(o, sh_x + e * 3, out + (seq * 34 + t) * 14);
}

// ---------- main kernel: 32 sequences/block, 17 warps, warp y does t=y then t=33-y ----------
__global__ void __launch_bounds__(544, 2)
tf_main(const int* __restrict__ idx, float* __restrict__ out) {
    __shared__ u32    sh_qb[NE * 3];
    __shared__ u64    sh_kv[NE * 5];
    __shared__ float2 sh_x[NE * 3];
    __shared__ u32    sh_c[32 * 9];   // packed u8 token-ids: lane-major, 9 words/lane

    const int NT = 544;
    int tid = threadIdx.y * 32 + threadIdx.x;
    int base = blockIdx.x * 32;

    for (int i = tid; i < NE * 3; i += NT) {
        sh_qb[i] = g_qb[i];
        sh_x[i]  = g_x[i];
    }
    for (int i = tid; i < NE * 5; i += NT) sh_kv[i] = g_kv[i];
    for (int i = tid; i < 32 * 9; i += NT) {
        int ln = i / 9, kg = i % 9;
        u32 w = 0;
        int kb = kg * 4;
#pragma unroll
        for (int j = 0; j < 4; j++) {
            int k = kb + j;
            if (k < T_SEQ) w |= ((u32)idx[(base + ln) * T_SEQ + k]) << (8 * j);
        }
        sh_c[ln * 9 + kg] = w;
    }
    __syncthreads();

    int lane = threadIdx.x, y = threadIdx.y;
    int seq = base + lane;

    attn_one(y, lane, seq, sh_qb, sh_kv, sh_x, sh_c, out);
    attn_one(33 - y, lane, seq, sh_qb, sh_kv, sh_x, sh_c, out);
}

extern "C" void kernel_launch(void* const* d_in, const int* in_sizes, int n_in,
                              void* d_out, int out_size) {
    const int*   idx     = (const int*)d_in[0];
    const float* tok_emb = (const float*)d_in[1];
    const float* pos_enc = (const float*)d_in[2];
    const float* wq      = (const float*)d_in[3];
    const float* wk      = (const float*)d_in[4];
    const float* wv      = (const float*)d_in[5];
    const float* wo      = (const float*)d_in[6];
    const float* ln1_g   = (const float*)d_in[7];
    const float* ln1_b   = (const float*)d_in[8];
    const float* ln2_g   = (const float*)d_in[9];
    const float* ln2_b   = (const float*)d_in[10];
    const float* w1      = (const float*)d_in[11];
    const float* b1      = (const float*)d_in[12];
    const float* w2      = (const float*)d_in[13];
    const float* b2      = (const float*)d_in[14];
    const float* lnf_g   = (const float*)d_in[15];
    const float* lnf_b   = (const float*)d_in[16];
    const float* wh      = (const float*)d_in[17];

    int nseq = in_sizes[0] / T_SEQ;

    build_luts<<<1, 512>>>(tok_emb, pos_enc, wq, wk, wv, ln1_g, ln1_b,
                           wo, w1, b1, w2, b2, ln2_g, ln2_b, lnf_g, lnf_b, wh);

    // copy staged weight block into constant memory (D2D memcpy: graph-capturable)
    void *c_addr = nullptr, *s_addr = nullptr;
    cudaGetSymbolAddress(&c_addr, c_sw);
    cudaGetSymbolAddress(&s_addr, g_sw);
    cudaMemcpyAsync(c_addr, s_addr, 288 * sizeof(float), cudaMemcpyDeviceToDevice);

    dim3 blk(32, 17);
    tf_main<<<nseq / 32, blk>>>(idx, (float*)d_out);
}